// round 1
// baseline (speedup 1.0000x reference)
#include <cuda_runtime.h>

// SSIM over 11x11 patches.
// img_pred: [4, 2048, 16, 121, 3] f32   (~190 MB)
// img_gt:   [2048, 16, 121, 3] f32      (~47.6 MB)
// out:      [4, 2048, 16] f32
//
// Strategy: one warp per output element (v,n,p). Lane l owns patches
// l, l+32, l+64, l+96 (3 contiguous channel floats each -> compile-time
// channel index, 15 register accumulators, no spill). Warp butterfly
// reduction, lane 0 computes the 3 per-channel SSIM values and the mean.
// View v is the fastest-varying warp coordinate so the 4 warps sharing a
// gt patch are in the same block (same SM) -> gt served from L1 for 3/4
// reads. Expected DRAM traffic ~238 MB -> HBM-bound ~35-50 us.

#define NV      4
#define NN      2048
#define NP      16
#define NPATCH  121
#define NC      3
#define ROW     (NPATCH * NC)   // 363 floats per (v,n,p)

__global__ __launch_bounds__(256) void ssim_kernel(
    const float* __restrict__ pred,
    const float* __restrict__ gt,
    float* __restrict__ out)
{
    __shared__ float w[NPATCH];

    const int tid = threadIdx.x;

    // Build the normalized gaussian window once per block.
    if (tid < NPATCH) {
        const float inv2s2 = 1.0f / 4.5f;   // 1/(2*sigma^2), sigma=1.5
        float S = 0.0f;
        #pragma unroll
        for (int i = 0; i < 11; i++) {
            float d = (float)(i - 5);
            S += expf(-d * d * inv2s2);
        }
        int py = tid / 11, px = tid % 11;
        float dy = (float)(py - 5), dx = (float)(px - 5);
        w[tid] = expf(-(dx * dx + dy * dy) * inv2s2) / (S * S);
    }
    __syncthreads();

    const int warp = blockIdx.x * (blockDim.x >> 5) + (tid >> 5);
    const int lane = tid & 31;

    // warp -> (n, p, v) with v fastest (gt reuse within the block / L1)
    const int v = warp & 3;
    const int q = warp >> 2;       // n*16 + p
    const int n = q >> 4;
    const int p = q & 15;

    const float* __restrict__ pbase = pred + (size_t)((v * NN + n) * NP + p) * ROW;
    const float* __restrict__ gbase = gt   + (size_t)(n * NP + p) * ROW;

    float m1[3] = {0.f, 0.f, 0.f};
    float m2[3] = {0.f, 0.f, 0.f};
    float p2[3] = {0.f, 0.f, 0.f};
    float g2[3] = {0.f, 0.f, 0.f};
    float pg[3] = {0.f, 0.f, 0.f};

    #pragma unroll
    for (int k = 0; k < 4; k++) {
        int patch = k * 32 + lane;
        if (patch < NPATCH) {
            float ww = w[patch];
            const float* pp = pbase + patch * 3;
            const float* gg = gbase + patch * 3;
            #pragma unroll
            for (int c = 0; c < 3; c++) {
                float a = pp[c];
                float b = gg[c];
                m1[c] += ww * a;
                m2[c] += ww * b;
                p2[c] += ww * a * a;
                g2[c] += ww * b * b;
                pg[c] += ww * a * b;
            }
        }
    }

    // Warp butterfly reduction of the 15 accumulators.
    #pragma unroll
    for (int off = 16; off; off >>= 1) {
        #pragma unroll
        for (int c = 0; c < 3; c++) {
            m1[c] += __shfl_xor_sync(0xFFFFFFFFu, m1[c], off);
            m2[c] += __shfl_xor_sync(0xFFFFFFFFu, m2[c], off);
            p2[c] += __shfl_xor_sync(0xFFFFFFFFu, p2[c], off);
            g2[c] += __shfl_xor_sync(0xFFFFFFFFu, g2[c], off);
            pg[c] += __shfl_xor_sync(0xFFFFFFFFu, pg[c], off);
        }
    }

    if (lane == 0) {
        const float C1 = 1e-4f;   // 0.01^2
        const float C2 = 9e-4f;   // 0.03^2
        float acc = 0.0f;
        #pragma unroll
        for (int c = 0; c < 3; c++) {
            float mu1 = m1[c], mu2 = m2[c];
            float mu1sq = mu1 * mu1;
            float mu2sq = mu2 * mu2;
            float mu12  = mu1 * mu2;
            float s1 = p2[c] - mu1sq;
            float s2 = g2[c] - mu2sq;
            float s12 = pg[c] - mu12;
            float num = (2.0f * mu12 + C1) * (2.0f * s12 + C2);
            float den = (mu1sq + mu2sq + C1) * (s1 + s2 + C2);
            acc += num / den;
        }
        out[(v * NN + n) * NP + p] = acc * (1.0f / 3.0f);
    }
}

extern "C" void kernel_launch(void* const* d_in, const int* in_sizes, int n_in,
                              void* d_out, int out_size)
{
    const float* pred = (const float*)d_in[0];   // img_pred [4,2048,16,121,3]
    const float* gt   = (const float*)d_in[1];   // img_gt   [2048,16,121,3]
    float* out = (float*)d_out;                  // [4,2048,16]

    // 4*2048*16 = 131072 outputs, one warp each; 8 warps per 256-thread block.
    const int total_warps = NV * NN * NP;
    const int warps_per_block = 8;
    const int blocks = total_warps / warps_per_block;  // 16384

    ssim_kernel<<<blocks, 256>>>(pred, gt, out);
}